// round 4
// baseline (speedup 1.0000x reference)
#include <cuda_runtime.h>
#include <math_constants.h>

// Problem constants
#define BB 2
#define CC 2048
#define NN 4096          // H*W = 64*64
#define K2C 4096         // 2*C
#define MQKV 6144        // C (Q) + C (K) + C (Vsum)

// Scratch (device globals — no allocations allowed)
__device__ float g_W[(long)MQKV * K2C];          // stacked weights [6144, 4096]
__device__ float g_bias[MQKV];
__device__ float g_QKV[(long)BB * MQKV * NN];    // Q|K|Vsum per batch
__device__ float g_S[(long)BB * NN * NN];        // pre-softmax logits

// ---------------------------------------------------------------------------
// prep: stack wq, wk, (wv_top+wv_bot) into g_W; biases into g_bias
// ---------------------------------------------------------------------------
__global__ void prep_kernel(const float* __restrict__ wq, const float* __restrict__ bq,
                            const float* __restrict__ wk, const float* __restrict__ bk,
                            const float* __restrict__ wv, const float* __restrict__ bv) {
    long i = (long)blockIdx.x * blockDim.x + threadIdx.x;
    long total = (long)MQKV * K2C;
    if (i < total) {
        int row = (int)(i >> 12);
        int col = (int)(i & 4095);
        float v;
        if (row < CC) {
            v = wq[i];
        } else if (row < 2 * CC) {
            v = wk[i - (long)CC * K2C];
        } else {
            int r = row - 2 * CC;
            v = wv[(long)r * K2C + col] + wv[(long)(r + CC) * K2C + col];
        }
        g_W[i] = v;
    }
    if (i < MQKV) {
        int row = (int)i;
        float b;
        if (row < CC)           b = bq[row];
        else if (row < 2 * CC)  b = bk[row - CC];
        else                    b = bv[row - 2 * CC] + bv[row - CC];
        g_bias[row] = b;
    }
}

// ---------------------------------------------------------------------------
// GEMM 1: QKV = g_W [6144,4096] @ X [4096,4096] + bias     (per batch)
//   X row k: k<2048 -> f_rgb[b,k,:], else f_i[b,k-2048,:]
//   Tiles 128x128x16, 256 threads, 8x8 microtile (split 4+4 to avoid conflicts)
// ---------------------------------------------------------------------------
__global__ __launch_bounds__(256, 2) void gemm_qkv_kernel(const float* __restrict__ frgb,
                                                          const float* __restrict__ fi) {
    __shared__ float As[16][132];   // As[k][m]  (W transposed)
    __shared__ float Bs[16][132];   // Bs[k][n]
    const int b  = blockIdx.z;
    const int m0 = blockIdx.y * 128;
    const int n0 = blockIdx.x * 128;
    const int tid = threadIdx.x;
    const int tx = tid & 15, ty = tid >> 4;

    float acc[8][8] = {};
    const float* xr = frgb + (long)b * CC * NN;
    const float* xi = fi   + (long)b * CC * NN;

    for (int k0 = 0; k0 < K2C; k0 += 16) {
        #pragma unroll
        for (int l = 0; l < 2; l++) {
            int idx = tid + l * 256;
            int row = idx >> 2;
            int kq  = (idx & 3) * 4;
            float4 w = *(const float4*)(g_W + (long)(m0 + row) * K2C + k0 + kq);
            As[kq + 0][row] = w.x; As[kq + 1][row] = w.y;
            As[kq + 2][row] = w.z; As[kq + 3][row] = w.w;
        }
        #pragma unroll
        for (int l = 0; l < 2; l++) {
            int idx = tid + l * 256;
            int krow = idx >> 5;
            int nq   = (idx & 31) * 4;
            int k = k0 + krow;
            const float* src = (k < CC) ? (xr + (long)k * NN) : (xi + (long)(k - CC) * NN);
            *(float4*)&Bs[krow][nq] = *(const float4*)(src + n0 + nq);
        }
        __syncthreads();
        #pragma unroll
        for (int k = 0; k < 16; k++) {
            float a[8], bb[8];
            *(float4*)&a[0]  = *(const float4*)&As[k][ty * 4];
            *(float4*)&a[4]  = *(const float4*)&As[k][ty * 4 + 64];
            *(float4*)&bb[0] = *(const float4*)&Bs[k][tx * 4];
            *(float4*)&bb[4] = *(const float4*)&Bs[k][tx * 4 + 64];
            #pragma unroll
            for (int i = 0; i < 8; i++)
                #pragma unroll
                for (int j = 0; j < 8; j++)
                    acc[i][j] += a[i] * bb[j];
        }
        __syncthreads();
    }
    float* out = g_QKV + (long)b * MQKV * NN;
    #pragma unroll
    for (int i = 0; i < 8; i++) {
        int r = m0 + ((i < 4) ? (ty * 4 + i) : (64 + ty * 4 + i - 4));
        float bias = g_bias[r];
        #pragma unroll
        for (int j = 0; j < 8; j++) {
            int c = n0 + ((j < 4) ? (tx * 4 + j) : (64 + tx * 4 + j - 4));
            out[(long)r * NN + c] = acc[i][j] + bias;
        }
    }
}

// ---------------------------------------------------------------------------
// GEMM 2: S[b][n][m] = (1/64) * sum_c Q[b][c][n] * K[b][c][m]
//   Both operands contiguous along output dims (no transpose in smem load)
// ---------------------------------------------------------------------------
__global__ __launch_bounds__(256, 2) void gemm_s_kernel() {
    __shared__ float As[16][132];   // As[c][n]
    __shared__ float Bs[16][132];   // Bs[c][m]
    const int b  = blockIdx.z;
    const int r0 = blockIdx.y * 128;   // n (output rows)
    const int m0 = blockIdx.x * 128;   // m (output cols)
    const int tid = threadIdx.x;
    const int tx = tid & 15, ty = tid >> 4;

    const float* Qb = g_QKV + (long)b * MQKV * NN;
    const float* Kb = Qb + (long)CC * NN;

    float acc[8][8] = {};
    for (int k0 = 0; k0 < CC; k0 += 16) {
        #pragma unroll
        for (int l = 0; l < 2; l++) {
            int idx = tid + l * 256;
            int krow = idx >> 5;
            int nq   = (idx & 31) * 4;
            *(float4*)&As[krow][nq] = *(const float4*)(Qb + (long)(k0 + krow) * NN + r0 + nq);
            *(float4*)&Bs[krow][nq] = *(const float4*)(Kb + (long)(k0 + krow) * NN + m0 + nq);
        }
        __syncthreads();
        #pragma unroll
        for (int k = 0; k < 16; k++) {
            float a[8], bb[8];
            *(float4*)&a[0]  = *(const float4*)&As[k][ty * 4];
            *(float4*)&a[4]  = *(const float4*)&As[k][ty * 4 + 64];
            *(float4*)&bb[0] = *(const float4*)&Bs[k][tx * 4];
            *(float4*)&bb[4] = *(const float4*)&Bs[k][tx * 4 + 64];
            #pragma unroll
            for (int i = 0; i < 8; i++)
                #pragma unroll
                for (int j = 0; j < 8; j++)
                    acc[i][j] += a[i] * bb[j];
        }
        __syncthreads();
    }
    float* Sb = g_S + (long)b * NN * NN;
    const float inv_scale = 0.015625f;   // 1/sqrt(4096)
    #pragma unroll
    for (int i = 0; i < 8; i++) {
        int r = r0 + ((i < 4) ? (ty * 4 + i) : (64 + ty * 4 + i - 4));
        #pragma unroll
        for (int j = 0; j < 8; j++) {
            int c = m0 + ((j < 4) ? (tx * 4 + j) : (64 + tx * 4 + j - 4));
            Sb[(long)r * NN + c] = acc[i][j] * inv_scale;
        }
    }
}

// ---------------------------------------------------------------------------
// softmax over last axis (m) of S -> attn (written straight into d_out)
// one block per row, 4096 elems, 16 per thread
// ---------------------------------------------------------------------------
__global__ __launch_bounds__(256) void softmax_kernel(float* __restrict__ attn) {
    const long row = blockIdx.x;
    const float* s = g_S + row * NN;
    float* o = attn + row * NN;
    const int tid = threadIdx.x;

    float v[16];
    #pragma unroll
    for (int i = 0; i < 4; i++)
        *(float4*)&v[i * 4] = *(const float4*)(s + tid * 4 + i * 1024);

    float mx = -CUDART_INF_F;
    #pragma unroll
    for (int i = 0; i < 16; i++) mx = fmaxf(mx, v[i]);

    __shared__ float red[8];
    #pragma unroll
    for (int off = 16; off > 0; off >>= 1)
        mx = fmaxf(mx, __shfl_xor_sync(0xffffffff, mx, off));
    if ((tid & 31) == 0) red[tid >> 5] = mx;
    __syncthreads();
    if (tid < 32) {
        float m = (tid < 8) ? red[tid] : -CUDART_INF_F;
        #pragma unroll
        for (int off = 4; off > 0; off >>= 1)
            m = fmaxf(m, __shfl_xor_sync(0xffffffff, m, off));
        if (tid == 0) red[0] = m;
    }
    __syncthreads();
    mx = red[0];
    __syncthreads();

    float sum = 0.f;
    #pragma unroll
    for (int i = 0; i < 16; i++) { v[i] = __expf(v[i] - mx); sum += v[i]; }
    #pragma unroll
    for (int off = 16; off > 0; off >>= 1)
        sum += __shfl_xor_sync(0xffffffff, sum, off);
    if ((tid & 31) == 0) red[tid >> 5] = sum;
    __syncthreads();
    if (tid < 32) {
        float m = (tid < 8) ? red[tid] : 0.f;
        #pragma unroll
        for (int off = 4; off > 0; off >>= 1)
            m += __shfl_xor_sync(0xffffffff, m, off);
        if (tid == 0) red[0] = m;
    }
    __syncthreads();
    float inv = 1.0f / red[0];

    #pragma unroll
    for (int i = 0; i < 16; i++) v[i] *= inv;
    #pragma unroll
    for (int i = 0; i < 4; i++)
        *(float4*)(o + tid * 4 + i * 1024) = *(const float4*)&v[i * 4];
}

// ---------------------------------------------------------------------------
// GEMM 3: f_final[b][c][n] = sum_m Vsum[b][c][m] * attn[b][n][m]
//   Both operands contiguous along the reduction dim -> transpose smem loads
// ---------------------------------------------------------------------------
__global__ __launch_bounds__(256, 2) void gemm_out_kernel(const float* __restrict__ attn,
                                                          float* __restrict__ f_final) {
    __shared__ float As[16][132];   // As[m][c]
    __shared__ float Bs[16][132];   // Bs[m][n]
    const int b  = blockIdx.z;
    const int c0 = blockIdx.y * 128;   // channel rows
    const int n0 = blockIdx.x * 128;   // pixel cols
    const int tid = threadIdx.x;
    const int tx = tid & 15, ty = tid >> 4;

    const float* Vb = g_QKV + (long)b * MQKV * NN + (long)(2 * CC) * NN;
    const float* Ab = attn + (long)b * NN * NN;

    float acc[8][8] = {};
    for (int k0 = 0; k0 < NN; k0 += 16) {
        #pragma unroll
        for (int l = 0; l < 2; l++) {
            int idx = tid + l * 256;
            int row = idx >> 2;
            int kq  = (idx & 3) * 4;
            float4 v = *(const float4*)(Vb + (long)(c0 + row) * NN + k0 + kq);
            As[kq + 0][row] = v.x; As[kq + 1][row] = v.y;
            As[kq + 2][row] = v.z; As[kq + 3][row] = v.w;
            float4 a = *(const float4*)(Ab + (long)(n0 + row) * NN + k0 + kq);
            Bs[kq + 0][row] = a.x; Bs[kq + 1][row] = a.y;
            Bs[kq + 2][row] = a.z; Bs[kq + 3][row] = a.w;
        }
        __syncthreads();
        #pragma unroll
        for (int k = 0; k < 16; k++) {
            float a[8], bb[8];
            *(float4*)&a[0]  = *(const float4*)&As[k][ty * 4];
            *(float4*)&a[4]  = *(const float4*)&As[k][ty * 4 + 64];
            *(float4*)&bb[0] = *(const float4*)&Bs[k][tx * 4];
            *(float4*)&bb[4] = *(const float4*)&Bs[k][tx * 4 + 64];
            #pragma unroll
            for (int i = 0; i < 8; i++)
                #pragma unroll
                for (int j = 0; j < 8; j++)
                    acc[i][j] += a[i] * bb[j];
        }
        __syncthreads();
    }
    #pragma unroll
    for (int i = 0; i < 8; i++) {
        int r = c0 + ((i < 4) ? (ty * 4 + i) : (64 + ty * 4 + i - 4));
        #pragma unroll
        for (int j = 0; j < 8; j++) {
            int c = n0 + ((j < 4) ? (tx * 4 + j) : (64 + tx * 4 + j - 4));
            f_final[((long)b * CC + r) * NN + c] = acc[i][j];
        }
    }
}

// ---------------------------------------------------------------------------
extern "C" void kernel_launch(void* const* d_in, const int* in_sizes, int n_in,
                              void* d_out, int out_size) {
    const float* frgb = (const float*)d_in[0];
    const float* fi   = (const float*)d_in[1];
    const float* wq   = (const float*)d_in[2];
    const float* bq   = (const float*)d_in[3];
    const float* wk   = (const float*)d_in[4];
    const float* bk   = (const float*)d_in[5];
    const float* wv   = (const float*)d_in[6];
    const float* bv   = (const float*)d_in[7];

    float* out = (float*)d_out;
    const long FSZ = (long)BB * CC * NN;      // 16,777,216
    float* f_final = out;
    float* out_rgb = out + FSZ;
    float* out_i   = out + 2 * FSZ;
    float* attn    = out + 3 * FSZ;

    long total = (long)MQKV * K2C;
    prep_kernel<<<(unsigned)((total + 255) / 256), 256>>>(wq, bq, wk, bk, wv, bv);

    dim3 g1(NN / 128, MQKV / 128, BB);
    gemm_qkv_kernel<<<g1, 256>>>(frgb, fi);

    dim3 g2(NN / 128, NN / 128, BB);
    gemm_s_kernel<<<g2, 256>>>();

    softmax_kernel<<<BB * NN, 256>>>(attn);

    dim3 g3(NN / 128, CC / 128, BB);
    gemm_out_kernel<<<g3, 256>>>(attn, f_final);

    cudaMemcpyAsync(out_rgb, frgb, FSZ * sizeof(float), cudaMemcpyDeviceToDevice);
    cudaMemcpyAsync(out_i,   fi,   FSZ * sizeof(float), cudaMemcpyDeviceToDevice);
}

// round 10
// speedup vs baseline: 3.1168x; 3.1168x over previous
#include <cuda_runtime.h>
#include <cuda_bf16.h>
#include <cstdint>
#include <math_constants.h>

#define BB 2
#define CC 2048
#define NN 4096
#define K2C 4096
typedef __nv_bfloat16 bf;

// smem layout per stage: Ah | Al | Bh | Bl, each 128 rows x 80B (32 bf16 + pad)
#define ROWB 80
#define HALF (128*ROWB)        // 10240
#define STG  (4*HALF)          // 40960
#define DSMEM (3*STG)          // 122880

// ---------------- scratch (device globals; allocation is forbidden) --------
__device__ bf g_XTh[(long)BB*NN*K2C], g_XTl[(long)BB*NN*K2C];
__device__ bf g_Wqkh[(long)K2C*K2C], g_Wqkl[(long)K2C*K2C];
__device__ bf g_Wvh[(long)CC*K2C],  g_Wvl[(long)CC*K2C];
__device__ bf g_Qh[(long)BB*NN*K2C], g_Ql[(long)BB*NN*K2C];   // [b][n][o]: Q | K
__device__ bf g_Vh[(long)BB*CC*NN],  g_Vl[(long)BB*CC*NN];
__device__ bf g_Ph[(long)BB*NN*NN],  g_Pl[(long)BB*NN*NN];    // attn hi/lo
__device__ float g_S[(long)BB*NN*NN];
__device__ float g_bqk[K2C], g_bv[CC];

// ---------------- helpers --------------------------------------------------
__device__ __forceinline__ uint32_t smem_u32(const void* p){
    uint32_t a; asm("{ .reg .u64 t; cvta.to.shared.u64 t, %1; cvt.u32.u64 %0, t; }":"=r"(a):"l"(p)); return a;
}
__device__ __forceinline__ void cp16(uint32_t d, const void* s){
    asm volatile("cp.async.cg.shared.global [%0], [%1], 16;" :: "r"(d), "l"(s));
}
__device__ __forceinline__ void ldsm4(uint32_t (&r)[4], uint32_t a){
    asm volatile("ldmatrix.sync.aligned.m8n8.x4.shared.b16 {%0,%1,%2,%3}, [%4];"
        : "=r"(r[0]),"=r"(r[1]),"=r"(r[2]),"=r"(r[3]) : "r"(a));
}
__device__ __forceinline__ void mma16816(float (&c)[4], const uint32_t (&a)[4], const uint32_t* b){
    asm volatile("mma.sync.aligned.m16n8k16.row.col.f32.bf16.bf16.f32 "
        "{%0,%1,%2,%3}, {%4,%5,%6,%7}, {%8,%9}, {%0,%1,%2,%3};"
        : "+f"(c[0]),"+f"(c[1]),"+f"(c[2]),"+f"(c[3])
        : "r"(a[0]),"r"(a[1]),"r"(a[2]),"r"(a[3]), "r"(b[0]),"r"(b[1]));
}
__device__ __forceinline__ void split2(float v, bf& h, bf& l){
    h = __float2bfloat16(v); l = __float2bfloat16(v - __bfloat162float(h));
}

// ---------------- prep kernels ---------------------------------------------
__global__ void k_w(const float* wq, const float* bq, const float* wk, const float* bk,
                    const float* wv, const float* bv){
    long i = (long)blockIdx.x*blockDim.x + threadIdx.x;
    if (i < (long)K2C*K2C){
        int o = (int)(i>>12);
        float v = (o<CC) ? wq[i] : wk[i-(long)CC*K2C];
        split2(v, g_Wqkh[i], g_Wqkl[i]);
    }
    if (i < (long)CC*K2C){
        float v = wv[i] + wv[i+(long)CC*K2C];
        split2(v, g_Wvh[i], g_Wvl[i]);
    }
    if (i < K2C) g_bqk[i] = (i<CC) ? bq[i] : bk[i-CC];
    if (i < CC)  g_bv[i]  = bv[i] + bv[i+CC];
}

__global__ void k_xt(const float* __restrict__ fr, const float* __restrict__ fi){
    __shared__ float t[32][33];
    int b = blockIdx.z, k0 = blockIdx.y*32, n0 = blockIdx.x*32;
    int tx = threadIdx.x, ty = threadIdx.y;
    #pragma unroll
    for (int i=0;i<4;i++){
        int k = k0 + ty + i*8;
        const float* s = (k<CC) ? (fr + ((long)b*CC + k)*NN) : (fi + ((long)b*CC + k - CC)*NN);
        t[ty+i*8][tx] = s[n0+tx];
    }
    __syncthreads();
    long base = (long)b*NN*K2C;
    #pragma unroll
    for (int i=0;i<4;i++){
        int n = n0 + ty + i*8;
        long o = base + (long)n*K2C + k0 + tx;
        split2(t[tx][ty+i*8], g_XTh[o], g_XTl[o]);
    }
}

// ---------------- bf16x3 split GEMM via mma.sync ---------------------------
// D[m][n] = alpha * sum_k A[m,k]*B[n,k] (+brow[m]) (+bcol[n])
// A [M,K] K-major (lda, batch stride sA); B [N,K] K-major (ldb, sB).
// Output: fp32 D, or bf16 hi/lo pair (Dh, Dl).
__global__ __launch_bounds__(256,1)
void k_gemm(const bf* __restrict__ Ah, const bf* __restrict__ Al, long lda, long sA,
            const bf* __restrict__ Bh, const bf* __restrict__ Bl, long ldb, long sB,
            float* D, bf* Dh, bf* Dl, long ldd, long sD, int K,
            const float* __restrict__ brow, const float* __restrict__ bcol, float alpha){
    extern __shared__ char smc[];
    const uint32_t sbase = smem_u32(smc);
    const int tid = threadIdx.x, lane = tid & 31, wid = tid >> 5;
    const int wm = wid & 3, wn = wid >> 2;          // warp grid 4(m) x 2(n), warp tile 32x64
    const int bz = blockIdx.z;
    const long m0 = (long)blockIdx.y*128, n0 = (long)blockIdx.x*128;

    const bf* pAh = Ah + (long)bz*sA + m0*lda;
    const bf* pAl = Al + (long)bz*sA + m0*lda;
    const bf* pBh = Bh + (long)bz*sB + n0*ldb;
    const bf* pBl = Bl + (long)bz*sB + n0*ldb;

    // cp.async producer: per stage, 4 halves x 128 rows x 4 chunks(16B) = 2048 cp16
    const int r1 = tid >> 2,        ch1 = tid & 3;         // rows 0..63
    auto load_stage = [&](int st, int kt){
        uint32_t sb = sbase + (uint32_t)st*STG;
        long kofs = (long)kt*32;
        #pragma unroll
        for (int i=0;i<2;i++){
            int row = r1 + i*64;
            uint32_t d = sb + row*ROWB + ch1*16;
            long g = (long)row*lda + kofs + ch1*8;
            cp16(d, pAh + g); cp16(d + HALF, pAl + g);
        }
        #pragma unroll
        for (int i=0;i<2;i++){
            int row = r1 + i*64;
            uint32_t d = sb + 2*HALF + row*ROWB + ch1*16;
            long g = (long)row*ldb + kofs + ch1*8;
            cp16(d, pBh + g); cp16(d + HALF, pBl + g);
        }
        asm volatile("cp.async.commit_group;" ::: "memory");
    };

    // ldmatrix lane offsets (row part + 16B chunk select for k-halves)
    uint32_t a_off[2], b_off[4];
    {
        int rr = (lane & 7) + ((lane >> 3) & 1) * 8;
        int kk = (lane >> 4) * 16;
        #pragma unroll
        for (int mf=0; mf<2; mf++) a_off[mf] = (uint32_t)((wm*32 + mf*16 + rr)*ROWB + kk);
        #pragma unroll
        for (int nf2=0; nf2<4; nf2++) b_off[nf2] = (uint32_t)(2*HALF + (wn*64 + nf2*16 + rr)*ROWB + kk);
    }

    float acc[2][8][4];
    #pragma unroll
    for (int i=0;i<2;i++)
        #pragma unroll
        for (int j=0;j<8;j++)
            #pragma unroll
            for (int q=0;q<4;q++) acc[i][j][q] = 0.f;

    const int KT = K / 32;
    load_stage(0, 0);
    load_stage(1, 1);

    for (int t=0; t<KT; t++){
        asm volatile("cp.async.wait_group 1;" ::: "memory");
        __syncthreads();
        uint32_t sb = sbase + (uint32_t)(t % 3)*STG;
        #pragma unroll
        for (int ks=0; ks<2; ks++){
            uint32_t ah[2][4], al[2][4], bh[8][2], bl[8][2], r[4];
            #pragma unroll
            for (int mf=0; mf<2; mf++){
                ldsm4(ah[mf], sb + a_off[mf] + ks*32);
                ldsm4(al[mf], sb + HALF + a_off[mf] + ks*32);
            }
            #pragma unroll
            for (int nf2=0; nf2<4; nf2++){
                ldsm4(r, sb + b_off[nf2] + ks*32);
                bh[nf2*2][0]=r[0]; bh[nf2*2][1]=r[2]; bh[nf2*2+1][0]=r[1]; bh[nf2*2+1][1]=r[3];
                ldsm4(r, sb + HALF + b_off[nf2] + ks*32);
                bl[nf2*2][0]=r[0]; bl[nf2*2][1]=r[2]; bl[nf2*2+1][0]=r[1]; bl[nf2*2+1][1]=r[3];
            }
            #pragma unroll
            for (int mf=0; mf<2; mf++)
                #pragma unroll
                for (int nf=0; nf<8; nf++){
                    mma16816(acc[mf][nf], ah[mf], bh[nf]);
                    mma16816(acc[mf][nf], ah[mf], bl[nf]);
                    mma16816(acc[mf][nf], al[mf], bh[nf]);
                }
        }
        if (t + 2 < KT) load_stage((t + 2) % 3, t + 2);
        else asm volatile("cp.async.commit_group;" ::: "memory");
    }

    // epilogue: c-frag lane l -> rows (l>>2, l>>2+8), cols 2(l&3)+{0,1}
    #pragma unroll
    for (int mf=0; mf<2; mf++){
        #pragma unroll
        for (int nf=0; nf<8; nf++){
            long col = n0 + wn*64 + nf*8 + (lane & 3)*2;
            #pragma unroll
            for (int half=0; half<2; half++){
                long row = m0 + wm*32 + mf*16 + (lane >> 2) + half*8;
                float v0 = acc[mf][nf][half*2+0]*alpha;
                float v1 = acc[mf][nf][half*2+1]*alpha;
                if (brow){ float b = brow[row]; v0 += b; v1 += b; }
                if (bcol){ v0 += bcol[col]; v1 += bcol[col+1]; }
                long o = (long)bz*sD + row*ldd + col;
                if (D){
                    *(float2*)(D + o) = make_float2(v0, v1);
                } else {
                    bf h0,l0,h1,l1; split2(v0,h0,l0); split2(v1,h1,l1);
                    *(__nv_bfloat162*)(Dh + o) = __nv_bfloat162(h0,h1);
                    *(__nv_bfloat162*)(Dl + o) = __nv_bfloat162(l0,l1);
                }
            }
        }
    }
}

// ---------------- softmax (fp32 attn to d_out + bf16 hi/lo for GEMM3) ------
__global__ __launch_bounds__(256) void k_softmax(float* __restrict__ attn){
    const long row = blockIdx.x;
    const float* s = g_S + row*NN;
    float* o = attn + row*NN;
    const int tid = threadIdx.x;
    float v[16];
    #pragma unroll
    for (int i=0;i<4;i++) *(float4*)&v[i*4] = *(const float4*)(s + tid*4 + i*1024);
    float mx = -CUDART_INF_F;
    #pragma unroll
    for (int i=0;i<16;i++) mx = fmaxf(mx, v[i]);
    __shared__ float red[8];
    #pragma unroll
    for (int off=16;off>0;off>>=1) mx = fmaxf(mx, __shfl_xor_sync(0xffffffff, mx, off));
    if ((tid&31)==0) red[tid>>5] = mx;
    __syncthreads();
    if (tid<32){
        float m = (tid<8)?red[tid]:-CUDART_INF_F;
        #pragma unroll
        for (int off=4;off>0;off>>=1) m = fmaxf(m, __shfl_xor_sync(0xffffffff, m, off));
        if (tid==0) red[0] = m;
    }
    __syncthreads(); mx = red[0]; __syncthreads();
    float sum = 0.f;
    #pragma unroll
    for (int i=0;i<16;i++){ v[i] = __expf(v[i]-mx); sum += v[i]; }
    #pragma unroll
    for (int off=16;off>0;off>>=1) sum += __shfl_xor_sync(0xffffffff, sum, off);
    if ((tid&31)==0) red[tid>>5] = sum;
    __syncthreads();
    if (tid<32){
        float m = (tid<8)?red[tid]:0.f;
        #pragma unroll
        for (int off=4;off>0;off>>=1) m += __shfl_xor_sync(0xffffffff, m, off);
        if (tid==0) red[0] = m;
    }
    __syncthreads();
    float inv = 1.0f/red[0];
    #pragma unroll
    for (int i=0;i<4;i++){
        #pragma unroll
        for (int j=0;j<4;j++) v[i*4+j] *= inv;
        long off = row*NN + tid*4 + i*1024;
        *(float4*)(o + tid*4 + i*1024) = *(const float4*)&v[i*4];
        bf h0,l0,h1,l1,h2,l2,h3,l3;
        split2(v[i*4+0],h0,l0); split2(v[i*4+1],h1,l1);
        split2(v[i*4+2],h2,l2); split2(v[i*4+3],h3,l3);
        *(__nv_bfloat162*)(g_Ph+off)   = __nv_bfloat162(h0,h1);
        *(__nv_bfloat162*)(g_Ph+off+2) = __nv_bfloat162(h2,h3);
        *(__nv_bfloat162*)(g_Pl+off)   = __nv_bfloat162(l0,l1);
        *(__nv_bfloat162*)(g_Pl+off+2) = __nv_bfloat162(l2,l3);
    }
}

// ---------------------------------------------------------------------------
extern "C" void kernel_launch(void* const* d_in, const int* in_sizes, int n_in,
                              void* d_out, int out_size){
    const float* frgb=(const float*)d_in[0]; const float* fi=(const float*)d_in[1];
    const float* wq=(const float*)d_in[2];   const float* bq=(const float*)d_in[3];
    const float* wk=(const float*)d_in[4];   const float* bk=(const float*)d_in[5];
    const float* wv=(const float*)d_in[6];   const float* bv=(const float*)d_in[7];

    float* out = (float*)d_out;
    const long FSZ = (long)BB*CC*NN;
    float* f_final = out;
    float* out_rgb = out + FSZ;
    float* out_i   = out + 2*FSZ;
    float* attn    = out + 3*FSZ;

    bf *XTh,*XTl,*Wqkh,*Wqkl,*Wvh,*Wvl,*Qh,*Ql,*Vh,*Vl,*Ph,*Pl;
    float *S,*bqk,*bvv;
    cudaGetSymbolAddress((void**)&XTh,g_XTh);  cudaGetSymbolAddress((void**)&XTl,g_XTl);
    cudaGetSymbolAddress((void**)&Wqkh,g_Wqkh);cudaGetSymbolAddress((void**)&Wqkl,g_Wqkl);
    cudaGetSymbolAddress((void**)&Wvh,g_Wvh);  cudaGetSymbolAddress((void**)&Wvl,g_Wvl);
    cudaGetSymbolAddress((void**)&Qh,g_Qh);    cudaGetSymbolAddress((void**)&Ql,g_Ql);
    cudaGetSymbolAddress((void**)&Vh,g_Vh);    cudaGetSymbolAddress((void**)&Vl,g_Vl);
    cudaGetSymbolAddress((void**)&Ph,g_Ph);    cudaGetSymbolAddress((void**)&Pl,g_Pl);
    cudaGetSymbolAddress((void**)&S,g_S);
    cudaGetSymbolAddress((void**)&bqk,g_bqk);  cudaGetSymbolAddress((void**)&bvv,g_bv);

    cudaFuncSetAttribute(k_gemm, cudaFuncAttributeMaxDynamicSharedMemorySize, DSMEM);

    k_w<<<(unsigned)(((long)K2C*K2C+255)/256), 256>>>(wq,bq,wk,bk,wv,bv);
    k_xt<<<dim3(NN/32, K2C/32, BB), dim3(32,8)>>>(frgb, fi);

    // G1qk: QK^T[b][n][o] = XT @ Wqk^T + bqk[o]   (M=NN, N=K2C, K=K2C)
    k_gemm<<<dim3(K2C/128, NN/128, BB), 256, DSMEM>>>(
        XTh,XTl,K2C,(long)NN*K2C, Wqkh,Wqkl,K2C,0,
        nullptr,Qh,Ql,K2C,(long)NN*K2C, K2C, nullptr,bqk,1.0f);
    // G1v: V[b][c][n] = Wv' @ XT^T + bv[c]        (M=CC, N=NN, K=K2C)
    k_gemm<<<dim3(NN/128, CC/128, BB), 256, DSMEM>>>(
        Wvh,Wvl,K2C,0, XTh,XTl,K2C,(long)NN*K2C,
        nullptr,Vh,Vl,NN,(long)CC*NN, K2C, bvv,nullptr,1.0f);
    // G2: S[b][n][m] = (1/64) Q . K               (M=NN, N=NN, K=CC)
    k_gemm<<<dim3(NN/128, NN/128, BB), 256, DSMEM>>>(
        Qh,Ql,K2C,(long)NN*K2C, Qh+CC,Ql+CC,K2C,(long)NN*K2C,
        S,nullptr,nullptr,NN,(long)NN*NN, CC, nullptr,nullptr,0.015625f);
    k_softmax<<<BB*NN,256>>>(attn);
    // G3: f_final[b][c][n] = V @ attn^T           (M=CC, N=NN, K=NN)
    k_gemm<<<dim3(NN/128, CC/128, BB), 256, DSMEM>>>(
        Vh,Vl,NN,(long)CC*NN, Ph,Pl,NN,(long)NN*NN,
        f_final,nullptr,nullptr,NN,(long)CC*NN, NN, nullptr,nullptr,1.0f);

    cudaMemcpyAsync(out_rgb, frgb, FSZ*sizeof(float), cudaMemcpyDeviceToDevice);
    cudaMemcpyAsync(out_i,   fi,   FSZ*sizeof(float), cudaMemcpyDeviceToDevice);
}

// round 12
// speedup vs baseline: 3.3727x; 1.0821x over previous
#include <cuda_runtime.h>
#include <cuda_bf16.h>
#include <cstdint>
#include <math_constants.h>

#define BB 2
#define CC 2048
#define NN 4096
#define K2C 4096
typedef __nv_bfloat16 bf;

// CTA tile 256(M) x 128(N), K-tile 32. smem rows: 32 bf16 = 64B data + pad -> 80B pitch
#define ROWB 80
#define AHALF (256*ROWB)       // 20480
#define BHALF (128*ROWB)       // 10240
#define STG   (2*AHALF+2*BHALF) // 61440
#define DSMEM (3*STG)           // 184320

// ---------------- scratch (device globals; allocation is forbidden) --------
__device__ bf g_XTh[(long)BB*NN*K2C], g_XTl[(long)BB*NN*K2C];
__device__ bf g_Wqkh[(long)K2C*K2C], g_Wqkl[(long)K2C*K2C];
__device__ bf g_Wvh[(long)CC*K2C],  g_Wvl[(long)CC*K2C];
__device__ bf g_Qh[(long)BB*NN*K2C], g_Ql[(long)BB*NN*K2C];   // [b][n][o]: Q | K
__device__ bf g_Vh[(long)BB*CC*NN],  g_Vl[(long)BB*CC*NN];
__device__ bf g_Ph[(long)BB*NN*NN],  g_Pl[(long)BB*NN*NN];    // attn hi/lo
__device__ float g_S[(long)BB*NN*NN];
__device__ float g_bqk[K2C], g_bv[CC];

// ---------------- helpers --------------------------------------------------
__device__ __forceinline__ uint32_t smem_u32(const void* p){
    uint32_t a; asm("{ .reg .u64 t; cvta.to.shared.u64 t, %1; cvt.u32.u64 %0, t; }":"=r"(a):"l"(p)); return a;
}
__device__ __forceinline__ void cp16(uint32_t d, const void* s){
    asm volatile("cp.async.cg.shared.global [%0], [%1], 16;" :: "r"(d), "l"(s));
}
__device__ __forceinline__ void ldsm4(uint32_t (&r)[4], uint32_t a){
    asm volatile("ldmatrix.sync.aligned.m8n8.x4.shared.b16 {%0,%1,%2,%3}, [%4];"
        : "=r"(r[0]),"=r"(r[1]),"=r"(r[2]),"=r"(r[3]) : "r"(a));
}
__device__ __forceinline__ void mma16816(float (&c)[4], const uint32_t (&a)[4], const uint32_t* b){
    asm volatile("mma.sync.aligned.m16n8k16.row.col.f32.bf16.bf16.f32 "
        "{%0,%1,%2,%3}, {%4,%5,%6,%7}, {%8,%9}, {%0,%1,%2,%3};"
        : "+f"(c[0]),"+f"(c[1]),"+f"(c[2]),"+f"(c[3])
        : "r"(a[0]),"r"(a[1]),"r"(a[2]),"r"(a[3]), "r"(b[0]),"r"(b[1]));
}
__device__ __forceinline__ void split2(float v, bf& h, bf& l){
    h = __float2bfloat16(v); l = __float2bfloat16(v - __bfloat162float(h));
}

// ---------------- prep kernels ---------------------------------------------
__global__ void k_w(const float* wq, const float* bq, const float* wk, const float* bk,
                    const float* wv, const float* bv){
    long i = (long)blockIdx.x*blockDim.x + threadIdx.x;
    if (i < (long)K2C*K2C){
        int o = (int)(i>>12);
        float v = (o<CC) ? wq[i] : wk[i-(long)CC*K2C];
        split2(v, g_Wqkh[i], g_Wqkl[i]);
    }
    if (i < (long)CC*K2C){
        float v = wv[i] + wv[i+(long)CC*K2C];
        split2(v, g_Wvh[i], g_Wvl[i]);
    }
    if (i < K2C) g_bqk[i] = (i<CC) ? bq[i] : bk[i-CC];
    if (i < CC)  g_bv[i]  = bv[i] + bv[i+CC];
}

__global__ void k_xt(const float* __restrict__ fr, const float* __restrict__ fi){
    __shared__ float t[32][33];
    int b = blockIdx.z, k0 = blockIdx.y*32, n0 = blockIdx.x*32;
    int tx = threadIdx.x, ty = threadIdx.y;
    #pragma unroll
    for (int i=0;i<4;i++){
        int k = k0 + ty + i*8;
        const float* s = (k<CC) ? (fr + ((long)b*CC + k)*NN) : (fi + ((long)b*CC + k - CC)*NN);
        t[ty+i*8][tx] = s[n0+tx];
    }
    __syncthreads();
    long base = (long)b*NN*K2C;
    #pragma unroll
    for (int i=0;i<4;i++){
        int n = n0 + ty + i*8;
        long o = base + (long)n*K2C + k0 + tx;
        split2(t[tx][ty+i*8], g_XTh[o], g_XTl[o]);
    }
}

// ---------------- bf16x3 split GEMM via mma.sync ---------------------------
// D[m][n] = alpha * sum_k A[m,k]*B[n,k] (+brow[m]) (+bcol[n])
// CTA 256x128, 512 threads, warp grid 4(m)x4(n), warp tile 64x32.
__global__ __launch_bounds__(512,1)
void k_gemm(const bf* __restrict__ Ah, const bf* __restrict__ Al, long lda, long sA,
            const bf* __restrict__ Bh, const bf* __restrict__ Bl, long ldb, long sB,
            float* D, bf* Dh, bf* Dl, long ldd, long sD, int K,
            const float* __restrict__ brow, const float* __restrict__ bcol, float alpha){
    extern __shared__ char smc[];
    const uint32_t sbase = smem_u32(smc);
    const int tid = threadIdx.x, lane = tid & 31, wid = tid >> 5;
    const int wm = wid >> 2, wn = wid & 3;          // 4x4 warp grid, warp tile 64x32
    const int bz = blockIdx.z;
    const long m0 = (long)blockIdx.y*256, n0 = (long)blockIdx.x*128;

    const bf* pAh = Ah + (long)bz*sA + m0*lda;
    const bf* pAl = Al + (long)bz*sA + m0*lda;
    const bf* pBh = Bh + (long)bz*sB + n0*ldb;
    const bf* pBl = Bl + (long)bz*sB + n0*ldb;

    // producer: A 256 rows x 4 chunks(16B) x {h,l}; B 128 rows x 4 x {h,l}
    auto load_stage = [&](int st, int kt){
        uint32_t sb = sbase + (uint32_t)st*STG;
        long kofs = (long)kt*32;
        #pragma unroll
        for (int i=0;i<2;i++){
            int s = tid + i*512;            // 0..1023
            int row = s >> 2, ch = s & 3;
            uint32_t d = sb + row*ROWB + ch*16;
            long g = (long)row*lda + kofs + ch*8;
            cp16(d, pAh + g); cp16(d + AHALF, pAl + g);
        }
        {
            int row = tid >> 2, ch = tid & 3;   // 128 rows
            uint32_t d = sb + 2*AHALF + row*ROWB + ch*16;
            long g = (long)row*ldb + kofs + ch*8;
            cp16(d, pBh + g); cp16(d + BHALF, pBl + g);
        }
        asm volatile("cp.async.commit_group;" ::: "memory");
    };

    // ldmatrix lane offsets
    uint32_t a_off[4], b_off[2];
    {
        int rr = (lane & 7) + ((lane >> 3) & 1) * 8;
        int kk = (lane >> 4) * 16;
        #pragma unroll
        for (int mf=0; mf<4; mf++) a_off[mf] = (uint32_t)((wm*64 + mf*16 + rr)*ROWB + kk);
        #pragma unroll
        for (int nf2=0; nf2<2; nf2++) b_off[nf2] = (uint32_t)(2*AHALF + (wn*32 + nf2*16 + rr)*ROWB + kk);
    }

    float acc[4][4][4];
    #pragma unroll
    for (int i=0;i<4;i++)
        #pragma unroll
        for (int j=0;j<4;j++)
            #pragma unroll
            for (int q=0;q<4;q++) acc[i][j][q] = 0.f;

    const int KT = K / 32;
    load_stage(0, 0);
    load_stage(1, 1);

    for (int t=0; t<KT; t++){
        asm volatile("cp.async.wait_group 1;" ::: "memory");
        __syncthreads();
        uint32_t sb = sbase + (uint32_t)(t % 3)*STG;
        #pragma unroll
        for (int ks=0; ks<2; ks++){
            uint32_t ah[4][4], al[4][4], bh[4][2], bl[4][2], r[4];
            #pragma unroll
            for (int nf2=0; nf2<2; nf2++){
                ldsm4(r, sb + b_off[nf2] + ks*32);
                bh[nf2*2][0]=r[0]; bh[nf2*2][1]=r[2]; bh[nf2*2+1][0]=r[1]; bh[nf2*2+1][1]=r[3];
                ldsm4(r, sb + BHALF + b_off[nf2] + ks*32);
                bl[nf2*2][0]=r[0]; bl[nf2*2][1]=r[2]; bl[nf2*2+1][0]=r[1]; bl[nf2*2+1][1]=r[3];
            }
            #pragma unroll
            for (int mf=0; mf<4; mf++){
                ldsm4(ah[mf], sb + a_off[mf] + ks*32);
                ldsm4(al[mf], sb + AHALF + a_off[mf] + ks*32);
            }
            #pragma unroll
            for (int mf=0; mf<4; mf++)
                #pragma unroll
                for (int nf=0; nf<4; nf++){
                    mma16816(acc[mf][nf], ah[mf], bh[nf]);
                    mma16816(acc[mf][nf], ah[mf], bl[nf]);
                    mma16816(acc[mf][nf], al[mf], bh[nf]);
                }
        }
        if (t + 2 < KT) load_stage((t + 2) % 3, t + 2);
        else asm volatile("cp.async.commit_group;" ::: "memory");
    }

    // epilogue: c-frag lane l -> rows (l>>2, +8), cols 2(l&3)+{0,1}
    #pragma unroll
    for (int mf=0; mf<4; mf++){
        #pragma unroll
        for (int nf=0; nf<4; nf++){
            long col = n0 + wn*32 + nf*8 + (lane & 3)*2;
            #pragma unroll
            for (int half=0; half<2; half++){
                long row = m0 + wm*64 + mf*16 + (lane >> 2) + half*8;
                float v0 = acc[mf][nf][half*2+0]*alpha;
                float v1 = acc[mf][nf][half*2+1]*alpha;
                if (brow){ float b = brow[row]; v0 += b; v1 += b; }
                if (bcol){ v0 += bcol[col]; v1 += bcol[col+1]; }
                long o = (long)bz*sD + row*ldd + col;
                if (D){
                    *(float2*)(D + o) = make_float2(v0, v1);
                } else {
                    bf h0,l0,h1,l1; split2(v0,h0,l0); split2(v1,h1,l1);
                    *(__nv_bfloat162*)(Dh + o) = __nv_bfloat162(h0,h1);
                    *(__nv_bfloat162*)(Dl + o) = __nv_bfloat162(l0,l1);
                }
            }
        }
    }
}

// ---------------- softmax (fp32 attn to d_out + bf16 hi/lo for GEMM3) ------
__global__ __launch_bounds__(256) void k_softmax(float* __restrict__ attn){
    const long row = blockIdx.x;
    const float* s = g_S + row*NN;
    float* o = attn + row*NN;
    const int tid = threadIdx.x;
    float v[16];
    #pragma unroll
    for (int i=0;i<4;i++) *(float4*)&v[i*4] = *(const float4*)(s + tid*4 + i*1024);
    float mx = -CUDART_INF_F;
    #pragma unroll
    for (int i=0;i<16;i++) mx = fmaxf(mx, v[i]);
    __shared__ float red[8];
    #pragma unroll
    for (int off=16;off>0;off>>=1) mx = fmaxf(mx, __shfl_xor_sync(0xffffffff, mx, off));
    if ((tid&31)==0) red[tid>>5] = mx;
    __syncthreads();
    if (tid<32){
        float m = (tid<8)?red[tid]:-CUDART_INF_F;
        #pragma unroll
        for (int off=4;off>0;off>>=1) m = fmaxf(m, __shfl_xor_sync(0xffffffff, m, off));
        if (tid==0) red[0] = m;
    }
    __syncthreads(); mx = red[0]; __syncthreads();
    float sum = 0.f;
    #pragma unroll
    for (int i=0;i<16;i++){ v[i] = __expf(v[i]-mx); sum += v[i]; }
    #pragma unroll
    for (int off=16;off>0;off>>=1) sum += __shfl_xor_sync(0xffffffff, sum, off);
    if ((tid&31)==0) red[tid>>5] = sum;
    __syncthreads();
    if (tid<32){
        float m = (tid<8)?red[tid]:0.f;
        #pragma unroll
        for (int off=4;off>0;off>>=1) m += __shfl_xor_sync(0xffffffff, m, off);
        if (tid==0) red[0] = m;
    }
    __syncthreads();
    float inv = 1.0f/red[0];
    #pragma unroll
    for (int i=0;i<4;i++){
        #pragma unroll
        for (int j=0;j<4;j++) v[i*4+j] *= inv;
        long off = row*NN + tid*4 + i*1024;
        *(float4*)(o + tid*4 + i*1024) = *(const float4*)&v[i*4];
        bf h0,l0,h1,l1,h2,l2,h3,l3;
        split2(v[i*4+0],h0,l0); split2(v[i*4+1],h1,l1);
        split2(v[i*4+2],h2,l2); split2(v[i*4+3],h3,l3);
        *(__nv_bfloat162*)(g_Ph+off)   = __nv_bfloat162(h0,h1);
        *(__nv_bfloat162*)(g_Ph+off+2) = __nv_bfloat162(h2,h3);
        *(__nv_bfloat162*)(g_Pl+off)   = __nv_bfloat162(l0,l1);
        *(__nv_bfloat162*)(g_Pl+off+2) = __nv_bfloat162(l2,l3);
    }
}

// ---------------------------------------------------------------------------
extern "C" void kernel_launch(void* const* d_in, const int* in_sizes, int n_in,
                              void* d_out, int out_size){
    const float* frgb=(const float*)d_in[0]; const float* fi=(const float*)d_in[1];
    const float* wq=(const float*)d_in[2];   const float* bq=(const float*)d_in[3];
    const float* wk=(const float*)d_in[4];   const float* bk=(const float*)d_in[5];
    const float* wv=(const float*)d_in[6];   const float* bv=(const float*)d_in[7];

    float* out = (float*)d_out;
    const long FSZ = (long)BB*CC*NN;
    float* f_final = out;
    float* out_rgb = out + FSZ;
    float* out_i   = out + 2*FSZ;
    float* attn    = out + 3*FSZ;

    bf *XTh,*XTl,*Wqkh,*Wqkl,*Wvh,*Wvl,*Qh,*Ql,*Vh,*Vl,*Ph,*Pl;
    float *S,*bqk,*bvv;
    cudaGetSymbolAddress((void**)&XTh,g_XTh);  cudaGetSymbolAddress((void**)&XTl,g_XTl);
    cudaGetSymbolAddress((void**)&Wqkh,g_Wqkh);cudaGetSymbolAddress((void**)&Wqkl,g_Wqkl);
    cudaGetSymbolAddress((void**)&Wvh,g_Wvh);  cudaGetSymbolAddress((void**)&Wvl,g_Wvl);
    cudaGetSymbolAddress((void**)&Qh,g_Qh);    cudaGetSymbolAddress((void**)&Ql,g_Ql);
    cudaGetSymbolAddress((void**)&Vh,g_Vh);    cudaGetSymbolAddress((void**)&Vl,g_Vl);
    cudaGetSymbolAddress((void**)&Ph,g_Ph);    cudaGetSymbolAddress((void**)&Pl,g_Pl);
    cudaGetSymbolAddress((void**)&S,g_S);
    cudaGetSymbolAddress((void**)&bqk,g_bqk);  cudaGetSymbolAddress((void**)&bvv,g_bv);

    cudaFuncSetAttribute(k_gemm, cudaFuncAttributeMaxDynamicSharedMemorySize, DSMEM);

    k_w<<<(unsigned)(((long)K2C*K2C+255)/256), 256>>>(wq,bq,wk,bk,wv,bv);
    k_xt<<<dim3(NN/32, K2C/32, BB), dim3(32,8)>>>(frgb, fi);

    // G1qk: QK^T[b][n][o] = XT @ Wqk^T + bqk[o]   (M=NN, N=K2C, K=K2C)
    k_gemm<<<dim3(K2C/128, NN/256, BB), 512, DSMEM>>>(
        XTh,XTl,K2C,(long)NN*K2C, Wqkh,Wqkl,K2C,0,
        nullptr,Qh,Ql,K2C,(long)NN*K2C, K2C, nullptr,bqk,1.0f);
    // G1v: V[b][c][n] = Wv' @ XT^T + bv[c]        (M=CC, N=NN, K=K2C)
    k_gemm<<<dim3(NN/128, CC/256, BB), 512, DSMEM>>>(
        Wvh,Wvl,K2C,0, XTh,XTl,K2C,(long)NN*K2C,
        nullptr,Vh,Vl,NN,(long)CC*NN, K2C, bvv,nullptr,1.0f);
    // G2: S[b][n][m] = (1/64) Q . K               (M=NN, N=NN, K=CC)
    k_gemm<<<dim3(NN/128, NN/256, BB), 512, DSMEM>>>(
        Qh,Ql,K2C,(long)NN*K2C, Qh+CC,Ql+CC,K2C,(long)NN*K2C,
        S,nullptr,nullptr,NN,(long)NN*NN, CC, nullptr,nullptr,0.015625f);
    k_softmax<<<BB*NN,256>>>(attn);
    // G3: f_final[b][c][n] = V @ attn^T           (M=CC, N=NN, K=NN)
    k_gemm<<<dim3(NN/128, CC/256, BB), 512, DSMEM>>>(
        Vh,Vl,NN,(long)CC*NN, Ph,Pl,NN,(long)NN*NN,
        f_final,nullptr,nullptr,NN,(long)CC*NN, NN, nullptr,nullptr,1.0f);

    cudaMemcpyAsync(out_rgb, frgb, FSZ*sizeof(float), cudaMemcpyDeviceToDevice);
    cudaMemcpyAsync(out_i,   fi,   FSZ*sizeof(float), cudaMemcpyDeviceToDevice);
}

// round 15
// speedup vs baseline: 4.1164x; 1.2205x over previous
#include <cuda_runtime.h>
#include <cuda_bf16.h>
#include <cstdint>
#include <math_constants.h>

#define BB 2
#define CC 2048
#define NN 4096
#define K2C 4096
typedef __nv_bfloat16 bf;

// CTA tile 128x128, K-tile 32. smem row = 64B (4 x 16B chunks, XOR-swizzled), no pad.
#define ROWB 64
#define HALF (128*ROWB)        // 8192
#define STG  (4*HALF)          // 32768  (Ah|Al|Bh|Bl)
#define DSMEM (3*STG)          // 98304 -> 2 CTAs/SM

// ---------------- scratch (device globals; allocation is forbidden) --------
__device__ bf g_XTh[(long)BB*NN*K2C], g_XTl[(long)BB*NN*K2C];
__device__ bf g_Wqkh[(long)K2C*K2C], g_Wqkl[(long)K2C*K2C];
__device__ bf g_Wvh[(long)CC*K2C],  g_Wvl[(long)CC*K2C];
__device__ bf g_Qh[(long)BB*NN*K2C], g_Ql[(long)BB*NN*K2C];   // [b][n][o]: Q | K
__device__ bf g_Vh[(long)BB*CC*NN],  g_Vl[(long)BB*CC*NN];
__device__ bf g_Ph[(long)BB*NN*NN],  g_Pl[(long)BB*NN*NN];    // attn hi/lo
__device__ float g_S[(long)BB*NN*NN];
__device__ float g_bqk[K2C], g_bv[CC];

// ---------------- helpers --------------------------------------------------
__device__ __forceinline__ uint32_t smem_u32(const void* p){
    uint32_t a; asm("{ .reg .u64 t; cvta.to.shared.u64 t, %1; cvt.u32.u64 %0, t; }":"=r"(a):"l"(p)); return a;
}
__device__ __forceinline__ void cp16(uint32_t d, const void* s){
    asm volatile("cp.async.cg.shared.global [%0], [%1], 16;" :: "r"(d), "l"(s));
}
__device__ __forceinline__ void ldsm4(uint32_t (&r)[4], uint32_t a){
    asm volatile("ldmatrix.sync.aligned.m8n8.x4.shared.b16 {%0,%1,%2,%3}, [%4];"
        : "=r"(r[0]),"=r"(r[1]),"=r"(r[2]),"=r"(r[3]) : "r"(a));
}
__device__ __forceinline__ void mma16816(float (&c)[4], const uint32_t (&a)[4], const uint32_t* b){
    asm volatile("mma.sync.aligned.m16n8k16.row.col.f32.bf16.bf16.f32 "
        "{%0,%1,%2,%3}, {%4,%5,%6,%7}, {%8,%9}, {%0,%1,%2,%3};"
        : "+f"(c[0]),"+f"(c[1]),"+f"(c[2]),"+f"(c[3])
        : "r"(a[0]),"r"(a[1]),"r"(a[2]),"r"(a[3]), "r"(b[0]),"r"(b[1]));
}
__device__ __forceinline__ void split2(float v, bf& h, bf& l){
    h = __float2bfloat16(v); l = __float2bfloat16(v - __bfloat162float(h));
}
// swizzled in-row chunk: chunk c (16B units) at row r -> c ^ ((r>>1)&3)
__device__ __forceinline__ uint32_t swz(int row, int ch){
    return (uint32_t)(row*ROWB + ((ch ^ ((row>>1)&3))<<4));
}

// ---------------- prep kernels ---------------------------------------------
__global__ void k_w(const float* wq, const float* bq, const float* wk, const float* bk,
                    const float* wv, const float* bv){
    long i = (long)blockIdx.x*blockDim.x + threadIdx.x;
    if (i < (long)K2C*K2C){
        int o = (int)(i>>12);
        float v = (o<CC) ? wq[i] : wk[i-(long)CC*K2C];
        split2(v, g_Wqkh[i], g_Wqkl[i]);
    }
    if (i < (long)CC*K2C){
        float v = wv[i] + wv[i+(long)CC*K2C];
        split2(v, g_Wvh[i], g_Wvl[i]);
    }
    if (i < K2C) g_bqk[i] = (i<CC) ? bq[i] : bk[i-CC];
    if (i < CC)  g_bv[i]  = bv[i] + bv[i+CC];
}

__global__ void k_xt(const float* __restrict__ fr, const float* __restrict__ fi){
    __shared__ float t[32][33];
    int b = blockIdx.z, k0 = blockIdx.y*32, n0 = blockIdx.x*32;
    int tx = threadIdx.x, ty = threadIdx.y;
    #pragma unroll
    for (int i=0;i<4;i++){
        int k = k0 + ty + i*8;
        const float* s = (k<CC) ? (fr + ((long)b*CC + k)*NN) : (fi + ((long)b*CC + k - CC)*NN);
        t[ty+i*8][tx] = s[n0+tx];
    }
    __syncthreads();
    long base = (long)b*NN*K2C;
    #pragma unroll
    for (int i=0;i<4;i++){
        int n = n0 + ty + i*8;
        long o = base + (long)n*K2C + k0 + tx;
        split2(t[tx][ty+i*8], g_XTh[o], g_XTl[o]);
    }
}

// ---------------- bf16x3 split GEMM via mma.sync ---------------------------
// D[m][n] = alpha * sum_k A[m,k]*B[n,k] (+brow[m]) (+bcol[n])
// CTA 128x128, 256 threads, warp grid 4(m)x2(n), warp tile 32x64. 2 CTAs/SM.
__global__ __launch_bounds__(256,2)
void k_gemm(const bf* __restrict__ Ah, const bf* __restrict__ Al, long lda, long sA,
            const bf* __restrict__ Bh, const bf* __restrict__ Bl, long ldb, long sB,
            float* D, bf* Dh, bf* Dl, long ldd, long sD, int K,
            const float* __restrict__ brow, const float* __restrict__ bcol, float alpha){
    extern __shared__ char smc[];
    const uint32_t sbase = smem_u32(smc);
    const int tid = threadIdx.x, lane = tid & 31, wid = tid >> 5;
    const int wm = wid & 3, wn = wid >> 2;          // 4x2 warp grid, warp tile 32x64
    const int bz = blockIdx.z;
    const long m0 = (long)blockIdx.y*128, n0 = (long)blockIdx.x*128;

    const bf* pAh = Ah + (long)bz*sA + m0*lda;
    const bf* pAl = Al + (long)bz*sA + m0*lda;
    const bf* pBh = Bh + (long)bz*sB + n0*ldb;
    const bf* pBl = Bl + (long)bz*sB + n0*ldb;

    // producer: per half 128 rows x 4 chunks = 512 cp16; 256 threads -> 2 each
    const int r1 = tid >> 2, ch1 = tid & 3;
    const uint32_t so0 = swz(r1, ch1), so1 = swz(r1 + 64, ch1);
    const long ga0 = (long)r1*lda + ch1*8, ga1 = (long)(r1+64)*lda + ch1*8;
    const long gb0 = (long)r1*ldb + ch1*8, gb1 = (long)(r1+64)*ldb + ch1*8;
    auto load_stage = [&](int st, int kt){
        uint32_t sb = sbase + (uint32_t)st*STG;
        long kofs = (long)kt*32;
        cp16(sb + so0,            pAh + ga0 + kofs);
        cp16(sb + so1,            pAh + ga1 + kofs);
        cp16(sb + HALF + so0,     pAl + ga0 + kofs);
        cp16(sb + HALF + so1,     pAl + ga1 + kofs);
        cp16(sb + 2*HALF + so0,   pBh + gb0 + kofs);
        cp16(sb + 2*HALF + so1,   pBh + gb1 + kofs);
        cp16(sb + 3*HALF + so0,   pBl + gb0 + kofs);
        cp16(sb + 3*HALF + so1,   pBl + gb1 + kofs);
        asm volatile("cp.async.commit_group;" ::: "memory");
    };

    // ldmatrix lane offsets, per k-half (ks) with swizzle
    uint32_t a_off[2][2], b_off[4][2];
    {
        int rr = (lane & 7) + ((lane >> 3) & 1) * 8;
        int cbase = (lane >> 4);                    // 0/1: 16B within k-half
        #pragma unroll
        for (int ks=0; ks<2; ks++){
            int ch = ks*2 + cbase;
            #pragma unroll
            for (int mf=0; mf<2; mf++) a_off[mf][ks] = swz(wm*32 + mf*16 + rr, ch);
            #pragma unroll
            for (int nf2=0; nf2<4; nf2++) b_off[nf2][ks] = 2*HALF + swz(wn*64 + nf2*16 + rr, ch);
        }
    }

    float acc[2][8][4];
    #pragma unroll
    for (int i=0;i<2;i++)
        #pragma unroll
        for (int j=0;j<8;j++)
            #pragma unroll
            for (int q=0;q<4;q++) acc[i][j][q] = 0.f;

    const int KT = K / 32;
    load_stage(0, 0);
    load_stage(1, 1);

    for (int t=0; t<KT; t++){
        asm volatile("cp.async.wait_group 1;" ::: "memory");
        __syncthreads();
        uint32_t sb = sbase + (uint32_t)(t % 3)*STG;
        #pragma unroll
        for (int ks=0; ks<2; ks++){
            uint32_t ah[2][4], al[2][4], bh[8][2], bl[8][2], r[4];
            #pragma unroll
            for (int mf=0; mf<2; mf++){
                ldsm4(ah[mf], sb + a_off[mf][ks]);
                ldsm4(al[mf], sb + HALF + a_off[mf][ks]);
            }
            #pragma unroll
            for (int nf2=0; nf2<4; nf2++){
                ldsm4(r, sb + b_off[nf2][ks]);
                bh[nf2*2][0]=r[0]; bh[nf2*2][1]=r[2]; bh[nf2*2+1][0]=r[1]; bh[nf2*2+1][1]=r[3];
                ldsm4(r, sb + HALF + b_off[nf2][ks]);
                bl[nf2*2][0]=r[0]; bl[nf2*2][1]=r[2]; bl[nf2*2+1][0]=r[1]; bl[nf2*2+1][1]=r[3];
            }
            #pragma unroll
            for (int mf=0; mf<2; mf++)
                #pragma unroll
                for (int nf=0; nf<8; nf++){
                    mma16816(acc[mf][nf], ah[mf], bh[nf]);
                    mma16816(acc[mf][nf], ah[mf], bl[nf]);
                    mma16816(acc[mf][nf], al[mf], bh[nf]);
                }
        }
        if (t + 2 < KT) load_stage((t + 2) % 3, t + 2);
        else asm volatile("cp.async.commit_group;" ::: "memory");
    }

    // epilogue: c-frag lane l -> rows (l>>2, +8), cols 2(l&3)+{0,1}
    #pragma unroll
    for (int mf=0; mf<2; mf++){
        #pragma unroll
        for (int nf=0; nf<8; nf++){
            long col = n0 + wn*64 + nf*8 + (lane & 3)*2;
            #pragma unroll
            for (int half=0; half<2; half++){
                long row = m0 + wm*32 + mf*16 + (lane >> 2) + half*8;
                float v0 = acc[mf][nf][half*2+0]*alpha;
                float v1 = acc[mf][nf][half*2+1]*alpha;
                if (brow){ float b = brow[row]; v0 += b; v1 += b; }
                if (bcol){ v0 += bcol[col]; v1 += bcol[col+1]; }
                long o = (long)bz*sD + row*ldd + col;
                if (D){
                    *(float2*)(D + o) = make_float2(v0, v1);
                } else {
                    bf h0,l0,h1,l1; split2(v0,h0,l0); split2(v1,h1,l1);
                    *(__nv_bfloat162*)(Dh + o) = __nv_bfloat162(h0,h1);
                    *(__nv_bfloat162*)(Dl + o) = __nv_bfloat162(l0,l1);
                }
            }
        }
    }
}

// ---------------- softmax (fp32 attn to d_out + bf16 hi/lo for GEMM3) ------
__global__ __launch_bounds__(256) void k_softmax(float* __restrict__ attn){
    const long row = blockIdx.x;
    const float* s = g_S + row*NN;
    float* o = attn + row*NN;
    const int tid = threadIdx.x;
    float v[16];
    #pragma unroll
    for (int i=0;i<4;i++) *(float4*)&v[i*4] = *(const float4*)(s + tid*4 + i*1024);
    float mx = -CUDART_INF_F;
    #pragma unroll
    for (int i=0;i<16;i++) mx = fmaxf(mx, v[i]);
    __shared__ float red[8];
    #pragma unroll
    for (int off=16;off>0;off>>=1) mx = fmaxf(mx, __shfl_xor_sync(0xffffffff, mx, off));
    if ((tid&31)==0) red[tid>>5] = mx;
    __syncthreads();
    if (tid<32){
        float m = (tid<8)?red[tid]:-CUDART_INF_F;
        #pragma unroll
        for (int off=4;off>0;off>>=1) m = fmaxf(m, __shfl_xor_sync(0xffffffff, m, off));
        if (tid==0) red[0] = m;
    }
    __syncthreads(); mx = red[0]; __syncthreads();
    float sum = 0.f;
    #pragma unroll
    for (int i=0;i<16;i++){ v[i] = __expf(v[i]-mx); sum += v[i]; }
    #pragma unroll
    for (int off=16;off>0;off>>=1) sum += __shfl_xor_sync(0xffffffff, sum, off);
    if ((tid&31)==0) red[tid>>5] = sum;
    __syncthreads();
    if (tid<32){
        float m = (tid<8)?red[tid]:0.f;
        #pragma unroll
        for (int off=4;off>0;off>>=1) m += __shfl_xor_sync(0xffffffff, m, off);
        if (tid==0) red[0] = m;
    }
    __syncthreads();
    float inv = 1.0f/red[0];
    #pragma unroll
    for (int i=0;i<4;i++){
        #pragma unroll
        for (int j=0;j<4;j++) v[i*4+j] *= inv;
        long off = row*NN + tid*4 + i*1024;
        *(float4*)(o + tid*4 + i*1024) = *(const float4*)&v[i*4];
        bf h0,l0,h1,l1,h2,l2,h3,l3;
        split2(v[i*4+0],h0,l0); split2(v[i*4+1],h1,l1);
        split2(v[i*4+2],h2,l2); split2(v[i*4+3],h3,l3);
        *(__nv_bfloat162*)(g_Ph+off)   = __nv_bfloat162(h0,h1);
        *(__nv_bfloat162*)(g_Ph+off+2) = __nv_bfloat162(h2,h3);
        *(__nv_bfloat162*)(g_Pl+off)   = __nv_bfloat162(l0,l1);
        *(__nv_bfloat162*)(g_Pl+off+2) = __nv_bfloat162(l2,l3);
    }
}

// ---------------------------------------------------------------------------
extern "C" void kernel_launch(void* const* d_in, const int* in_sizes, int n_in,
                              void* d_out, int out_size){
    const float* frgb=(const float*)d_in[0]; const float* fi=(const float*)d_in[1];
    const float* wq=(const float*)d_in[2];   const float* bq=(const float*)d_in[3];
    const float* wk=(const float*)d_in[4];   const float* bk=(const float*)d_in[5];
    const float* wv=(const float*)d_in[6];   const float* bv=(const float*)d_in[7];

    float* out = (float*)d_out;
    const long FSZ = (long)BB*CC*NN;
    float* f_final = out;
    float* out_rgb = out + FSZ;
    float* out_i   = out + 2*FSZ;
    float* attn    = out + 3*FSZ;

    bf *XTh,*XTl,*Wqkh,*Wqkl,*Wvh,*Wvl,*Qh,*Ql,*Vh,*Vl,*Ph,*Pl;
    float *S,*bqk,*bvv;
    cudaGetSymbolAddress((void**)&XTh,g_XTh);  cudaGetSymbolAddress((void**)&XTl,g_XTl);
    cudaGetSymbolAddress((void**)&Wqkh,g_Wqkh);cudaGetSymbolAddress((void**)&Wqkl,g_Wqkl);
    cudaGetSymbolAddress((void**)&Wvh,g_Wvh);  cudaGetSymbolAddress((void**)&Wvl,g_Wvl);
    cudaGetSymbolAddress((void**)&Qh,g_Qh);    cudaGetSymbolAddress((void**)&Ql,g_Ql);
    cudaGetSymbolAddress((void**)&Vh,g_Vh);    cudaGetSymbolAddress((void**)&Vl,g_Vl);
    cudaGetSymbolAddress((void**)&Ph,g_Ph);    cudaGetSymbolAddress((void**)&Pl,g_Pl);
    cudaGetSymbolAddress((void**)&S,g_S);
    cudaGetSymbolAddress((void**)&bqk,g_bqk);  cudaGetSymbolAddress((void**)&bvv,g_bv);

    cudaFuncSetAttribute(k_gemm, cudaFuncAttributeMaxDynamicSharedMemorySize, DSMEM);

    k_w<<<(unsigned)(((long)K2C*K2C+255)/256), 256>>>(wq,bq,wk,bk,wv,bv);
    k_xt<<<dim3(NN/32, K2C/32, BB), dim3(32,8)>>>(frgb, fi);

    // G1qk: QK^T[b][n][o] = XT @ Wqk^T + bqk[o]   (M=NN, N=K2C, K=K2C)
    k_gemm<<<dim3(K2C/128, NN/128, BB), 256, DSMEM>>>(
        XTh,XTl,K2C,(long)NN*K2C, Wqkh,Wqkl,K2C,0,
        nullptr,Qh,Ql,K2C,(long)NN*K2C, K2C, nullptr,bqk,1.0f);
    // G1v: V[b][c][n] = Wv' @ XT^T + bv[c]        (M=CC, N=NN, K=K2C)
    k_gemm<<<dim3(NN/128, CC/128, BB), 256, DSMEM>>>(
        Wvh,Wvl,K2C,0, XTh,XTl,K2C,(long)NN*K2C,
        nullptr,Vh,Vl,NN,(long)CC*NN, K2C, bvv,nullptr,1.0f);
    // G2: S[b][n][m] = (1/64) Q . K               (M=NN, N=NN, K=CC)
    k_gemm<<<dim3(NN/128, NN/128, BB), 256, DSMEM>>>(
        Qh,Ql,K2C,(long)NN*K2C, Qh+CC,Ql+CC,K2C,(long)NN*K2C,
        S,nullptr,nullptr,NN,(long)NN*NN, CC, nullptr,nullptr,0.015625f);
    k_softmax<<<BB*NN,256>>>(attn);
    // G3: f_final[b][c][n] = V @ attn^T           (M=CC, N=NN, K=NN)
    k_gemm<<<dim3(NN/128, CC/128, BB), 256, DSMEM>>>(
        Vh,Vl,NN,(long)CC*NN, Ph,Pl,NN,(long)NN*NN,
        f_final,nullptr,nullptr,NN,(long)CC*NN, NN, nullptr,nullptr,1.0f);

    cudaMemcpyAsync(out_rgb, frgb, FSZ*sizeof(float), cudaMemcpyDeviceToDevice);
    cudaMemcpyAsync(out_i,   fi,   FSZ*sizeof(float), cudaMemcpyDeviceToDevice);
}